// round 1
// baseline (speedup 1.0000x reference)
#include <cuda_runtime.h>
#include <math.h>

#define BB 8
#define MM 3072
#define CC 10
#define HH 128
#define KK 32
#define RADIUSF 0.04f
#define ACC_SCALEF 0.02f
#define MAX_VELF 0.02f
#define NOISEF 0.002f

// Scratch (no cudaMalloc allowed): neighbor lists
__device__ int g_nbr_idx[BB * MM * KK];
__device__ int g_nbr_cnt[BB * MM];

// ---------------------------------------------------------------------------
// Kernel A: brute-force toroidal neighbor search, keep K nearest within RADIUS
// One thread per particle; all batch positions staged in shared memory.
// ---------------------------------------------------------------------------
#define TPB_A 128
__global__ void __launch_bounds__(TPB_A) nbr_kernel(const float* __restrict__ x)
{
    __shared__ float2 sp[MM];
    const int bpb = MM / TPB_A;                 // 24 blocks per batch
    const int b = blockIdx.x / bpb;
    const int i = (blockIdx.x % bpb) * TPB_A + threadIdx.x;
    const float* xb = x + (size_t)b * MM * CC;

    for (int j = threadIdx.x; j < MM; j += TPB_A) {
        const float* r = xb + (size_t)j * CC;
        sp[j] = make_float2(r[0], r[1]);
    }
    __syncthreads();

    const float xi = sp[i].x, yi = sp[i].y;

    float nd2[KK];
    int   nidx[KK];
    int   cnt = 0;
    float dmax = 1e30f;
    int   amax = 0;

    #pragma unroll 4
    for (int j = 0; j < MM; j++) {
        float2 pj = sp[j];
        float dx = xi - pj.x; dx -= rintf(dx);
        float dy = yi - pj.y; dy -= rintf(dy);
        float d2 = dx * dx + dy * dy + 1e-12f;
        float dist = sqrtf(d2);
        if (dist < RADIUSF && j != i) {
            if (cnt < KK) {
                nd2[cnt] = d2; nidx[cnt] = j; cnt++;
                if (cnt == KK) {
                    dmax = -1.0f;
                    #pragma unroll
                    for (int t = 0; t < KK; t++)
                        if (nd2[t] > dmax) { dmax = nd2[t]; amax = t; }
                }
            } else if (d2 < dmax) {
                nd2[amax] = d2; nidx[amax] = j;
                dmax = -1.0f;
                #pragma unroll
                for (int t = 0; t < KK; t++)
                    if (nd2[t] > dmax) { dmax = nd2[t]; amax = t; }
            }
        }
    }

    const int base = b * MM + i;
    g_nbr_cnt[base] = cnt;
    for (int e = 0; e < cnt; e++) g_nbr_idx[(size_t)base * KK + e] = nidx[e];
}

// ---------------------------------------------------------------------------
// Kernel B: per-edge MLP (12->128->2 effective) + particle state update.
// One warp per particle. W1 columns register-resident (4 hidden units/lane).
// ---------------------------------------------------------------------------
#define WARPS_B 8
__global__ void __launch_bounds__(WARPS_B * 32) mlp_kernel(
    const float* __restrict__ x,  const float* __restrict__ W1,
    const float* __restrict__ b1, const float* __restrict__ W2,
    const float* __restrict__ b2, const float* __restrict__ noise_u,
    float* __restrict__ out)
{
    const int warp = threadIdx.x >> 5;
    const int lane = threadIdx.x & 31;
    const int g = blockIdx.x * WARPS_B + warp;      // 0 .. B*M-1
    const int b = g / MM;

    const float* xi = x + (size_t)g * CC;
    const float pix = xi[0], piy = xi[1];
    const float cell = xi[4];
    const bool  is_cell = (cell == 1.0f);

    const int cnt = g_nbr_cnt[g];
    const int* __restrict__ nbr = g_nbr_idx + (size_t)g * KK;

    int   deg_cell = 0;
    float o0 = 0.0f, o1 = 0.0f;

    if (is_cell) {
        // W1 columns for hidden units h = lane + 32*r
        float w1r[12][4];
        #pragma unroll
        for (int f = 0; f < 12; f++)
            #pragma unroll
            for (int r = 0; r < 4; r++)
                w1r[f][r] = __ldg(&W1[f * HH + lane + 32 * r]);
        float b1r[4];
        #pragma unroll
        for (int r = 0; r < 4; r++) b1r[r] = __ldg(&b1[lane + 32 * r]);

        float agg[4] = {0.f, 0.f, 0.f, 0.f};

        for (int e = 0; e < cnt; e++) {
            const int j = nbr[e];
            const float2* xj = (const float2*)(x + ((size_t)b * MM + j) * CC);
            float2 v0 = __ldg(&xj[0]);   // pos
            float2 v1 = __ldg(&xj[1]);   // vel
            float2 v2 = __ldg(&xj[2]);   // cell, rest0
            float2 v3 = __ldg(&xj[3]);   // rest1, rest2
            float2 v4 = __ldg(&xj[4]);   // rest3, rest4

            float dx = pix - v0.x; dx -= rintf(dx);
            float dy = piy - v0.y; dy -= rintf(dy);
            float edist = sqrtf(dx * dx + dy * dy + 1e-12f);

            float msg[12];
            msg[0] = v1.x; msg[1] = v1.y; msg[2] = v2.x; msg[3] = v2.y;
            msg[4] = v3.x; msg[5] = v3.y; msg[6] = v4.x; msg[7] = v4.y;
            msg[8] = edist; msg[9] = dx; msg[10] = dy; msg[11] = v2.x;

            if (v2.x == 1.0f) deg_cell++;

            #pragma unroll
            for (int r = 0; r < 4; r++) {
                float t = b1r[r];
                #pragma unroll
                for (int f = 0; f < 12; f++) t = fmaf(msg[f], w1r[f][r], t);
                agg[r] += fmaxf(t, 0.0f);
            }
        }

        // agg @ W2[:, 0:2]  (outputs 2..6 are dead code in the reference)
        #pragma unroll
        for (int r = 0; r < 4; r++) {
            const int h = lane + 32 * r;
            o0 = fmaf(agg[r], __ldg(&W2[h * 7 + 0]), o0);
            o1 = fmaf(agg[r], __ldg(&W2[h * 7 + 1]), o1);
        }
        #pragma unroll
        for (int s = 16; s > 0; s >>= 1) {
            o0 += __shfl_xor_sync(0xffffffffu, o0, s);
            o1 += __shfl_xor_sync(0xffffffffu, o1, s);
        }
        o0 += __ldg(&b2[0]);
        o1 += __ldg(&b2[1]);
    } else {
        // Only deg_cell is needed for non-cell particles
        for (int e = 0; e < cnt; e++) {
            const int j = nbr[e];
            float c4 = __ldg(&x[((size_t)b * MM + j) * CC + 4]);
            if (c4 == 1.0f) deg_cell++;
        }
    }

    if (lane == 0) {
        const float vx = xi[2], vy = xi[3];
        float nvx = vx, nvy = vy, npx = pix, npy = piy;

        if (is_cell) {
            float ax = tanhf(o0) * ACC_SCALEF;
            float ay = tanhf(o1) * ACC_SCALEF;
            float ux = vx + ax, uy = vy + ay;
            float sp = sqrtf(ux * ux + uy * uy);
            float sc = fminf(1.0f, MAX_VELF / (sp + 1e-12f));
            ux *= sc; uy *= sc;
            npx = pix + ux; npx -= floorf(npx);
            npy = piy + uy; npy -= floorf(npy);
            const float* nu = noise_u + (size_t)g * 3;
            float u0 = nu[0], u1 = nu[1], u2 = nu[2];
            float nm = (u2 > 0.5f) ? 1.0f : 0.0f;
            nvx = ux + (u0 * 2.0f - 1.0f) * NOISEF * nm;
            nvy = uy + (u1 * 2.0f - 1.0f) * NOISEF * nm;
        }

        const bool dead     =  is_cell && (deg_cell < 1);
        const bool consumed = !is_cell && (deg_cell >= 1);
        const float keep = (dead || consumed) ? 0.0f : 1.0f;

        float* o = out + (size_t)g * CC;
        o[0] = npx * keep; o[1] = npy * keep;
        o[2] = nvx * keep; o[3] = nvy * keep;
        o[4] = xi[4] * keep;
        o[5] = xi[5] * keep;
        o[6] = xi[6] * keep;
        o[7] = xi[7] * keep;
        o[8] = xi[8] * keep;
        o[9] = xi[9] * keep;
    }
}

// ---------------------------------------------------------------------------
extern "C" void kernel_launch(void* const* d_in, const int* in_sizes, int n_in,
                              void* d_out, int out_size)
{
    const float* x       = (const float*)d_in[0];
    const float* W1      = (const float*)d_in[1];
    const float* b1      = (const float*)d_in[2];
    const float* W2      = (const float*)d_in[3];
    const float* b2      = (const float*)d_in[4];
    const float* noise_u = (const float*)d_in[5];
    float* out = (float*)d_out;

    nbr_kernel<<<BB * (MM / TPB_A), TPB_A>>>(x);
    mlp_kernel<<<(BB * MM) / WARPS_B, WARPS_B * 32>>>(x, W1, b1, W2, b2, noise_u, out);
}

// round 2
// speedup vs baseline: 3.0020x; 3.0020x over previous
#include <cuda_runtime.h>
#include <math.h>

#define BB 8
#define MM 3072
#define CC 10
#define HH 128
#define KK 32
#define GG 24                 // grid cells per axis; 1/24 > 0.04 radius
#define NCELL (GG * GG)       // 576
#define RADIUSF 0.04f
#define ACC_SCALEF 0.02f
#define MAX_VELF 0.02f
#define NOISEF 0.002f

// Scratch (no cudaMalloc allowed)
__device__ int    g_nbr_idx[BB * MM * KK];
__device__ int    g_nbr_cnt[BB * MM];
__device__ float4 g_sorted[BB * MM];            // {x, y, id_as_float_bits, pad}
__device__ int    g_cell_off[BB * (NCELL + 1)]; // exclusive offsets per batch

__device__ __forceinline__ int cell_of(float p) {
    int c = (int)(p * (float)GG);
    return c > GG - 1 ? GG - 1 : c;
}

// ---------------------------------------------------------------------------
// Kernel 0: build cell-sorted particle list. One block per batch.
// ---------------------------------------------------------------------------
#define TPB_G 1024
__global__ void __launch_bounds__(TPB_G) build_grid_kernel(const float* __restrict__ x)
{
    __shared__ int s_cnt[NCELL];
    __shared__ int s_scan[TPB_G];
    __shared__ int s_cur[NCELL];

    const int b = blockIdx.x;
    const int tid = threadIdx.x;
    const float* xb = x + (size_t)b * MM * CC;

    if (tid < NCELL) s_cnt[tid] = 0;
    __syncthreads();

    // pass 1: count
    int   myc[MM / TPB_G];
    float mpx[MM / TPB_G], mpy[MM / TPB_G];
    #pragma unroll
    for (int r = 0; r < MM / TPB_G; r++) {
        const int i = tid + r * TPB_G;
        const float px = xb[(size_t)i * CC + 0];
        const float py = xb[(size_t)i * CC + 1];
        const int c = cell_of(py) * GG + cell_of(px);
        myc[r] = c; mpx[r] = px; mpy[r] = py;
        atomicAdd(&s_cnt[c], 1);
    }
    __syncthreads();

    // inclusive Hillis-Steele scan over NCELL (padded to TPB_G)
    s_scan[tid] = (tid < NCELL) ? s_cnt[tid] : 0;
    __syncthreads();
    for (int off = 1; off < TPB_G; off <<= 1) {
        int v = (tid >= off) ? s_scan[tid - off] : 0;
        __syncthreads();
        s_scan[tid] += v;
        __syncthreads();
    }
    // exclusive offsets + cursors
    if (tid < NCELL) {
        int excl = s_scan[tid] - s_cnt[tid];
        s_cur[tid] = excl;
        g_cell_off[b * (NCELL + 1) + tid] = excl;
    }
    if (tid == 0) g_cell_off[b * (NCELL + 1) + NCELL] = MM;
    __syncthreads();

    // pass 2: scatter
    #pragma unroll
    for (int r = 0; r < MM / TPB_G; r++) {
        const int i = tid + r * TPB_G;
        const int slot = atomicAdd(&s_cur[myc[r]], 1);
        g_sorted[(size_t)b * MM + slot] =
            make_float4(mpx[r], mpy[r], __int_as_float(i), 0.0f);
    }
}

// ---------------------------------------------------------------------------
// Kernel A: grid neighbor search. One thread per SORTED slot (spatial locality
// within a warp -> L1 broadcast of candidate cells).
// ---------------------------------------------------------------------------
#define TPB_A 128
__global__ void __launch_bounds__(TPB_A) nbr_kernel()
{
    const int s = blockIdx.x * TPB_A + threadIdx.x;     // global sorted slot
    const int b = s / MM;
    const int myslot = s - b * MM;

    const float4 me = g_sorted[s];
    const float xi = me.x, yi = me.y;
    const int   myid = __float_as_int(me.z);

    const int cix = cell_of(xi);
    const int ciy = cell_of(yi);
    const int obase = b * (NCELL + 1);
    const float4* __restrict__ sb = g_sorted + (size_t)b * MM;

    float nd2[KK];
    int   cnt = 0;
    float dmax = 1e30f;
    int   amax = 0;
    const int gbase = (b * MM + myid) * KK;

    #pragma unroll
    for (int dyc = -1; dyc <= 1; dyc++) {
        int cy = ciy + dyc; if (cy < 0) cy += GG; if (cy >= GG) cy -= GG;
        #pragma unroll
        for (int dxc = -1; dxc <= 1; dxc++) {
            int cx = cix + dxc; if (cx < 0) cx += GG; if (cx >= GG) cx -= GG;
            const int c = cy * GG + cx;
            const int t0 = g_cell_off[obase + c];
            const int t1 = g_cell_off[obase + c + 1];
            for (int t = t0; t < t1; t++) {
                const float4 cand = __ldg(&sb[t]);
                float dx = xi - cand.x; dx -= rintf(dx);
                float dy = yi - cand.y; dy -= rintf(dy);
                const float d2 = dx * dx + dy * dy + 1e-12f;
                const float dist = sqrtf(d2);
                if (dist < RADIUSF && t != myslot) {
                    const int cid = __float_as_int(cand.z);
                    if (cnt < KK) {
                        nd2[cnt] = d2;
                        g_nbr_idx[gbase + cnt] = cid;
                        cnt++;
                        if (cnt == KK) {
                            dmax = -1.0f;
                            #pragma unroll
                            for (int q = 0; q < KK; q++)
                                if (nd2[q] > dmax) { dmax = nd2[q]; amax = q; }
                        }
                    } else if (d2 < dmax) {
                        nd2[amax] = d2;
                        g_nbr_idx[gbase + amax] = cid;
                        dmax = -1.0f;
                        #pragma unroll
                        for (int q = 0; q < KK; q++)
                            if (nd2[q] > dmax) { dmax = nd2[q]; amax = q; }
                    }
                }
            }
        }
    }
    g_nbr_cnt[b * MM + myid] = cnt;
}

// ---------------------------------------------------------------------------
// Kernel B: per-edge MLP (12->128->2 effective) + particle update.
// One warp per particle, software-pipelined gathers.
// ---------------------------------------------------------------------------
#define WARPS_B 8
__global__ void __launch_bounds__(WARPS_B * 32) mlp_kernel(
    const float* __restrict__ x,  const float* __restrict__ W1,
    const float* __restrict__ b1, const float* __restrict__ W2,
    const float* __restrict__ b2, const float* __restrict__ noise_u,
    float* __restrict__ out)
{
    const unsigned FULL = 0xffffffffu;
    const int warp = threadIdx.x >> 5;
    const int lane = threadIdx.x & 31;
    const int g = blockIdx.x * WARPS_B + warp;      // 0 .. B*M-1
    const int b = g / MM;

    const float* xi = x + (size_t)g * CC;
    const float pix = xi[0], piy = xi[1];
    const bool  is_cell = (xi[4] == 1.0f);

    const int cnt = g_nbr_cnt[g];
    const int* __restrict__ nbr = g_nbr_idx + (size_t)g * KK;

    // lane-parallel: neighbor indices + deg_cell via ballot (also warms L1)
    const int nbr_l = (lane < cnt) ? __ldg(&nbr[lane]) : 0;
    float c4l = 0.0f;
    if (lane < cnt)
        c4l = __ldg(&x[((size_t)b * MM + nbr_l) * CC + 4]);
    const int deg_cell = __popc(__ballot_sync(FULL, (lane < cnt) && (c4l == 1.0f)));

    float o0 = 0.0f, o1 = 0.0f;

    if (is_cell && cnt > 0) {
        // W1 columns for hidden units h = lane + 32*r
        float w1r[12][4];
        #pragma unroll
        for (int f = 0; f < 12; f++)
            #pragma unroll
            for (int r = 0; r < 4; r++)
                w1r[f][r] = __ldg(&W1[f * HH + lane + 32 * r]);
        float b1r[4];
        #pragma unroll
        for (int r = 0; r < 4; r++) b1r[r] = __ldg(&b1[lane + 32 * r]);

        float agg[4] = {0.f, 0.f, 0.f, 0.f};

        // prefetch edge 0
        int jj = __shfl_sync(FULL, nbr_l, 0);
        const float2* xp = (const float2*)(x + ((size_t)b * MM + jj) * CC);
        float2 c0 = __ldg(&xp[0]), c1 = __ldg(&xp[1]), c2 = __ldg(&xp[2]);
        float2 c3 = __ldg(&xp[3]), c4 = __ldg(&xp[4]);

        for (int e = 0; e < cnt; e++) {
            const float2 v0 = c0, v1 = c1, v2 = c2, v3 = c3, v4 = c4;
            if (e + 1 < cnt) {               // prefetch next edge
                jj = __shfl_sync(FULL, nbr_l, e + 1);
                xp = (const float2*)(x + ((size_t)b * MM + jj) * CC);
                c0 = __ldg(&xp[0]); c1 = __ldg(&xp[1]); c2 = __ldg(&xp[2]);
                c3 = __ldg(&xp[3]); c4 = __ldg(&xp[4]);
            }

            float dx = pix - v0.x; dx -= rintf(dx);
            float dy = piy - v0.y; dy -= rintf(dy);
            const float edist = sqrtf(dx * dx + dy * dy + 1e-12f);

            float msg[12];
            msg[0] = v1.x; msg[1] = v1.y; msg[2] = v2.x; msg[3] = v2.y;
            msg[4] = v3.x; msg[5] = v3.y; msg[6] = v4.x; msg[7] = v4.y;
            msg[8] = edist; msg[9] = dx; msg[10] = dy; msg[11] = v2.x;

            #pragma unroll
            for (int r = 0; r < 4; r++) {
                float t = b1r[r];
                #pragma unroll
                for (int f = 0; f < 12; f++) t = fmaf(msg[f], w1r[f][r], t);
                agg[r] += fmaxf(t, 0.0f);
            }
        }

        // agg @ W2[:, 0:2]  (outputs 2..6 are dead code in the reference)
        #pragma unroll
        for (int r = 0; r < 4; r++) {
            const int h = lane + 32 * r;
            o0 = fmaf(agg[r], __ldg(&W2[h * 7 + 0]), o0);
            o1 = fmaf(agg[r], __ldg(&W2[h * 7 + 1]), o1);
        }
        #pragma unroll
        for (int s = 16; s > 0; s >>= 1) {
            o0 += __shfl_xor_sync(FULL, o0, s);
            o1 += __shfl_xor_sync(FULL, o1, s);
        }
        o0 += __ldg(&b2[0]);
        o1 += __ldg(&b2[1]);
    }

    if (lane == 0) {
        const float vx = xi[2], vy = xi[3];
        float nvx = vx, nvy = vy, npx = pix, npy = piy;

        if (is_cell) {
            float ax = tanhf(o0) * ACC_SCALEF;
            float ay = tanhf(o1) * ACC_SCALEF;
            float ux = vx + ax, uy = vy + ay;
            float sp = sqrtf(ux * ux + uy * uy);
            float sc = fminf(1.0f, MAX_VELF / (sp + 1e-12f));
            ux *= sc; uy *= sc;
            npx = pix + ux; npx -= floorf(npx);
            npy = piy + uy; npy -= floorf(npy);
            const float* nu = noise_u + (size_t)g * 3;
            float u0 = nu[0], u1 = nu[1], u2 = nu[2];
            float nm = (u2 > 0.5f) ? 1.0f : 0.0f;
            nvx = ux + (u0 * 2.0f - 1.0f) * NOISEF * nm;
            nvy = uy + (u1 * 2.0f - 1.0f) * NOISEF * nm;
        }

        const bool dead     =  is_cell && (deg_cell < 1);
        const bool consumed = !is_cell && (deg_cell >= 1);
        const float keep = (dead || consumed) ? 0.0f : 1.0f;

        float* o = out + (size_t)g * CC;
        o[0] = npx * keep; o[1] = npy * keep;
        o[2] = nvx * keep; o[3] = nvy * keep;
        o[4] = xi[4] * keep;
        o[5] = xi[5] * keep;
        o[6] = xi[6] * keep;
        o[7] = xi[7] * keep;
        o[8] = xi[8] * keep;
        o[9] = xi[9] * keep;
    }
}

// ---------------------------------------------------------------------------
extern "C" void kernel_launch(void* const* d_in, const int* in_sizes, int n_in,
                              void* d_out, int out_size)
{
    const float* x       = (const float*)d_in[0];
    const float* W1      = (const float*)d_in[1];
    const float* b1      = (const float*)d_in[2];
    const float* W2      = (const float*)d_in[3];
    const float* b2      = (const float*)d_in[4];
    const float* noise_u = (const float*)d_in[5];
    float* out = (float*)d_out;

    build_grid_kernel<<<BB, TPB_G>>>(x);
    nbr_kernel<<<(BB * MM) / TPB_A, TPB_A>>>();
    mlp_kernel<<<(BB * MM) / WARPS_B, WARPS_B * 32>>>(x, W1, b1, W2, b2, noise_u, out);
}

// round 3
// speedup vs baseline: 4.8442x; 1.6137x over previous
#include <cuda_runtime.h>
#include <math.h>

#define BB 8
#define MM 3072
#define CC 10
#define HH 128
#define KK 32
#define GG 24                 // grid cells per axis; 1/24 > 0.04 radius
#define NCELL (GG * GG)       // 576
#define CAP 64                // per-warp hit capacity (P(hits>64) ~ 1e-20 at lambda~15)
#define RADIUSF 0.04f
#define ACC_SCALEF 0.02f
#define MAX_VELF 0.02f
#define NOISEF 0.002f

// Scratch (no cudaMalloc allowed)
__device__ float4 g_sorted[BB * MM];            // {x, y, id_as_float_bits, pad}
__device__ int    g_cell_off[BB * (NCELL + 1)]; // exclusive offsets per batch

__device__ __forceinline__ int cell_of(float p) {
    int c = (int)(p * (float)GG);
    return c > GG - 1 ? GG - 1 : c;
}

// ---------------------------------------------------------------------------
// Kernel 0: build cell-sorted particle list. One block per batch.
// ---------------------------------------------------------------------------
#define TPB_G 1024
__global__ void __launch_bounds__(TPB_G) build_grid_kernel(const float* __restrict__ x)
{
    __shared__ int s_cnt[NCELL];
    __shared__ int s_scan[TPB_G];
    __shared__ int s_cur[NCELL];

    const int b = blockIdx.x;
    const int tid = threadIdx.x;
    const float* xb = x + (size_t)b * MM * CC;

    if (tid < NCELL) s_cnt[tid] = 0;
    __syncthreads();

    int   myc[MM / TPB_G];
    float mpx[MM / TPB_G], mpy[MM / TPB_G];
    #pragma unroll
    for (int r = 0; r < MM / TPB_G; r++) {
        const int i = tid + r * TPB_G;
        const float px = xb[(size_t)i * CC + 0];
        const float py = xb[(size_t)i * CC + 1];
        const int c = cell_of(py) * GG + cell_of(px);
        myc[r] = c; mpx[r] = px; mpy[r] = py;
        atomicAdd(&s_cnt[c], 1);
    }
    __syncthreads();

    s_scan[tid] = (tid < NCELL) ? s_cnt[tid] : 0;
    __syncthreads();
    for (int off = 1; off < TPB_G; off <<= 1) {
        int v = (tid >= off) ? s_scan[tid - off] : 0;
        __syncthreads();
        s_scan[tid] += v;
        __syncthreads();
    }
    if (tid < NCELL) {
        int excl = s_scan[tid] - s_cnt[tid];
        s_cur[tid] = excl;
        g_cell_off[b * (NCELL + 1) + tid] = excl;
    }
    if (tid == 0) g_cell_off[b * (NCELL + 1) + NCELL] = MM;
    __syncthreads();

    #pragma unroll
    for (int r = 0; r < MM / TPB_G; r++) {
        const int i = tid + r * TPB_G;
        const int slot = atomicAdd(&s_cur[myc[r]], 1);
        g_sorted[(size_t)b * MM + slot] =
            make_float4(mpx[r], mpy[r], __int_as_float(i), 0.0f);
    }
}

// ---------------------------------------------------------------------------
// Fused kernel: warp-per-particle. Lane-parallel 3x3-cell neighbor search into
// per-warp smem, then hidden-per-lane edge MLP with prefetch pipelining.
// ---------------------------------------------------------------------------
#define WARPS_F 8
__global__ void __launch_bounds__(WARPS_F * 32) fused_kernel(
    const float* __restrict__ x,  const float* __restrict__ W1,
    const float* __restrict__ b1, const float* __restrict__ W2,
    const float* __restrict__ b2, const float* __restrict__ noise_u,
    float* __restrict__ out)
{
    __shared__ int   s_j   [WARPS_F][CAP];
    __shared__ float s_dx  [WARPS_F][CAP];
    __shared__ float s_dy  [WARPS_F][CAP];
    __shared__ float s_dist[WARPS_F][CAP];
    __shared__ int   s_astart[WARPS_F][9];   // cell start minus prefix
    __shared__ int   s_bound [WARPS_F][10];  // prefix bounds

    const unsigned FULL = 0xffffffffu;
    const int warp = threadIdx.x >> 5;
    const int lane = threadIdx.x & 31;
    const int s = blockIdx.x * WARPS_F + warp;   // global sorted slot
    const int b = s / MM;
    const int myslot = s - b * MM;

    const float4 me = g_sorted[s];
    const float pix = me.x, piy = me.y;
    const int   myid = __float_as_int(me.z);
    const int   grow = b * MM + myid;            // row in x / out

    // ---- lane-parallel candidate enumeration --------------------------------
    {
        const int cix = cell_of(pix);
        const int ciy = cell_of(piy);
        int len = 0, t0 = 0;
        if (lane < 9) {
            int cy = ciy + (lane / 3) - 1; if (cy < 0) cy += GG; if (cy >= GG) cy -= GG;
            int cx = cix + (lane % 3) - 1; if (cx < 0) cx += GG; if (cx >= GG) cx -= GG;
            const int c = cy * GG + cx;
            t0      = g_cell_off[b * (NCELL + 1) + c];
            len     = g_cell_off[b * (NCELL + 1) + c + 1] - t0;
        }
        // inclusive scan of len over lanes 0..8
        int incl = len;
        #pragma unroll
        for (int o = 1; o < 16; o <<= 1) {
            int v = __shfl_up_sync(FULL, incl, o);
            if (lane >= o) incl += v;
        }
        const int T = __shfl_sync(FULL, incl, 8);
        if (lane < 9) {
            const int excl = incl - len;
            s_astart[warp][lane] = t0 - excl;
            s_bound [warp][lane] = excl;
        }
        if (lane == 0) s_bound[warp][9] = T;
        __syncwarp();

        const float4* __restrict__ sb = g_sorted + (size_t)b * MM;
        int hits = 0;
        for (int base = 0; base < T; base += 32) {
            const int k = base + lane;
            bool pred = false;
            int  cid = 0;
            float dx = 0.f, dy = 0.f, dist = 0.f;
            if (k < T) {
                int q = 0;
                #pragma unroll
                for (int t = 1; t < 9; t++)
                    if (k >= s_bound[warp][t]) q = t;
                const int tslot = s_astart[warp][q] + k;
                const float4 cand = __ldg(&sb[tslot]);
                dx = pix - cand.x; dx -= rintf(dx);
                dy = piy - cand.y; dy -= rintf(dy);
                dist = sqrtf(dx * dx + dy * dy + 1e-12f);
                pred = (dist < RADIUSF) && (tslot != myslot);
                cid = __float_as_int(cand.z);
            }
            const unsigned m = __ballot_sync(FULL, pred);
            if (pred) {
                const int pos = hits + __popc(m & ((1u << lane) - 1));
                if (pos < CAP) {
                    s_j   [warp][pos] = cid;
                    s_dx  [warp][pos] = dx;
                    s_dy  [warp][pos] = dy;
                    s_dist[warp][pos] = dist;
                }
            }
            hits += __popc(m);
        }
        if (hits > CAP) hits = CAP;
        __syncwarp();

        // rare: rank-select 32 nearest
        if (hits > KK) {
            int   rj[2];  float rdx[2], rdy[2], rds[2];  int rk[2];
            int nkeep = 0;
            for (int h = lane; h < hits; h += 32) {
                const float dh = s_dist[warp][h];
                int rank = 0;
                for (int g2 = 0; g2 < hits; g2++) {
                    const float dg = s_dist[warp][g2];
                    rank += (dg < dh) || (dg == dh && g2 < h);
                }
                if (rank < KK) {
                    rj[nkeep] = s_j[warp][h];  rdx[nkeep] = s_dx[warp][h];
                    rdy[nkeep] = s_dy[warp][h]; rds[nkeep] = dh; rk[nkeep] = rank;
                    nkeep++;
                }
            }
            __syncwarp();
            for (int t = 0; t < nkeep; t++) {
                s_j   [warp][rk[t]] = rj[t];
                s_dx  [warp][rk[t]] = rdx[t];
                s_dy  [warp][rk[t]] = rdy[t];
                s_dist[warp][rk[t]] = rds[t];
            }
            hits = KK;
            __syncwarp();
        }
        if (lane == 0) s_bound[warp][9] = hits;   // stash cnt
        __syncwarp();
    }
    const int cnt = s_bound[warp][9];

    // ---- deg_cell (lane-parallel, warms L1 for the gather loop) -------------
    const float* xi = x + (size_t)grow * CC;
    const bool is_cell = (xi[4] == 1.0f);
    float c4l = 0.0f;
    if (lane < cnt)
        c4l = __ldg(&x[((size_t)b * MM + s_j[warp][lane]) * CC + 4]);
    const int deg_cell = __popc(__ballot_sync(FULL, (lane < cnt) && (c4l == 1.0f)));

    float o0 = 0.0f, o1 = 0.0f;

    if (is_cell) {
        float agg[4] = {0.f, 0.f, 0.f, 0.f};
        if (cnt > 0) {
            float w1r[12][4];
            #pragma unroll
            for (int f = 0; f < 12; f++)
                #pragma unroll
                for (int r = 0; r < 4; r++)
                    w1r[f][r] = __ldg(&W1[f * HH + lane + 32 * r]);
            float b1r[4];
            #pragma unroll
            for (int r = 0; r < 4; r++) b1r[r] = __ldg(&b1[lane + 32 * r]);

            // prefetch edge 0 (fields 2..9 of neighbor row)
            int jj = s_j[warp][0];
            const float2* xp = (const float2*)(x + ((size_t)b * MM + jj) * CC);
            float2 c1 = __ldg(&xp[1]), c2 = __ldg(&xp[2]);
            float2 c3 = __ldg(&xp[3]), c4 = __ldg(&xp[4]);

            for (int e = 0; e < cnt; e++) {
                const float2 v1 = c1, v2 = c2, v3 = c3, v4 = c4;
                const float dx = s_dx[warp][e], dy = s_dy[warp][e];
                const float edist = s_dist[warp][e];
                if (e + 1 < cnt) {
                    jj = s_j[warp][e + 1];
                    xp = (const float2*)(x + ((size_t)b * MM + jj) * CC);
                    c1 = __ldg(&xp[1]); c2 = __ldg(&xp[2]);
                    c3 = __ldg(&xp[3]); c4 = __ldg(&xp[4]);
                }

                float msg[12];
                msg[0] = v1.x; msg[1] = v1.y; msg[2] = v2.x; msg[3] = v2.y;
                msg[4] = v3.x; msg[5] = v3.y; msg[6] = v4.x; msg[7] = v4.y;
                msg[8] = edist; msg[9] = dx; msg[10] = dy; msg[11] = v2.x;

                #pragma unroll
                for (int r = 0; r < 4; r++) {
                    float t = b1r[r];
                    #pragma unroll
                    for (int f = 0; f < 12; f++) t = fmaf(msg[f], w1r[f][r], t);
                    agg[r] += fmaxf(t, 0.0f);
                }
            }
        }

        // agg @ W2[:, 0:2]  (outputs 2..6 are dead code in the reference)
        #pragma unroll
        for (int r = 0; r < 4; r++) {
            const int h = lane + 32 * r;
            o0 = fmaf(agg[r], __ldg(&W2[h * 7 + 0]), o0);
            o1 = fmaf(agg[r], __ldg(&W2[h * 7 + 1]), o1);
        }
        #pragma unroll
        for (int sh = 16; sh > 0; sh >>= 1) {
            o0 += __shfl_xor_sync(FULL, o0, sh);
            o1 += __shfl_xor_sync(FULL, o1, sh);
        }
        o0 += __ldg(&b2[0]);
        o1 += __ldg(&b2[1]);
    }

    if (lane == 0) {
        const float vx = xi[2], vy = xi[3];
        float nvx = vx, nvy = vy, npx = pix, npy = piy;

        if (is_cell) {
            float ax = tanhf(o0) * ACC_SCALEF;
            float ay = tanhf(o1) * ACC_SCALEF;
            float ux = vx + ax, uy = vy + ay;
            float sp = sqrtf(ux * ux + uy * uy);
            float sc = fminf(1.0f, MAX_VELF / (sp + 1e-12f));
            ux *= sc; uy *= sc;
            npx = pix + ux; npx -= floorf(npx);
            npy = piy + uy; npy -= floorf(npy);
            const float* nu = noise_u + (size_t)grow * 3;
            float u0 = nu[0], u1 = nu[1], u2 = nu[2];
            float nm = (u2 > 0.5f) ? 1.0f : 0.0f;
            nvx = ux + (u0 * 2.0f - 1.0f) * NOISEF * nm;
            nvy = uy + (u1 * 2.0f - 1.0f) * NOISEF * nm;
        }

        const bool dead     =  is_cell && (deg_cell < 1);
        const bool consumed = !is_cell && (deg_cell >= 1);
        const float keep = (dead || consumed) ? 0.0f : 1.0f;

        float* o = out + (size_t)grow * CC;
        o[0] = npx * keep; o[1] = npy * keep;
        o[2] = nvx * keep; o[3] = nvy * keep;
        o[4] = xi[4] * keep;
        o[5] = xi[5] * keep;
        o[6] = xi[6] * keep;
        o[7] = xi[7] * keep;
        o[8] = xi[8] * keep;
        o[9] = xi[9] * keep;
    }
}

// ---------------------------------------------------------------------------
extern "C" void kernel_launch(void* const* d_in, const int* in_sizes, int n_in,
                              void* d_out, int out_size)
{
    const float* x       = (const float*)d_in[0];
    const float* W1      = (const float*)d_in[1];
    const float* b1      = (const float*)d_in[2];
    const float* W2      = (const float*)d_in[3];
    const float* b2      = (const float*)d_in[4];
    const float* noise_u = (const float*)d_in[5];
    float* out = (float*)d_out;

    build_grid_kernel<<<BB, TPB_G>>>(x);
    fused_kernel<<<(BB * MM) / WARPS_F, WARPS_F * 32>>>(x, W1, b1, W2, b2, noise_u, out);
}

// round 4
// speedup vs baseline: 5.6215x; 1.1605x over previous
#include <cuda_runtime.h>
#include <math.h>

#define BB 8
#define MM 3072
#define CC 10
#define HH 128
#define KK 32
#define GG 24                 // grid cells per axis; 1/24 > 0.04 radius
#define NCELL (GG * GG)       // 576
#define CAP 64                // per-particle hit capacity (P(>64) ~ 0 at lambda~15)
#define NP 4                  // particles per 256-thread block
#define RADIUSF 0.04f
#define ACC_SCALEF 0.02f
#define MAX_VELF 0.02f
#define NOISEF 0.002f

// Scratch (no cudaMalloc allowed)
__device__ float4 g_sorted[BB * MM];            // {x, y, id_as_float_bits, pad}
__device__ int    g_cell_off[BB * (NCELL + 1)]; // exclusive offsets per batch

__device__ __forceinline__ int cell_of(float p) {
    int c = (int)(p * (float)GG);
    return c > GG - 1 ? GG - 1 : c;
}

// ---------------------------------------------------------------------------
// Kernel 0: build cell-sorted particle list. One block per batch.
// ---------------------------------------------------------------------------
#define TPB_G 1024
__global__ void __launch_bounds__(TPB_G) build_grid_kernel(const float* __restrict__ x)
{
    __shared__ int s_cnt[NCELL];
    __shared__ int s_scan[TPB_G];
    __shared__ int s_cur[NCELL];

    const int b = blockIdx.x;
    const int tid = threadIdx.x;
    const float* xb = x + (size_t)b * MM * CC;

    if (tid < NCELL) s_cnt[tid] = 0;
    __syncthreads();

    int   myc[MM / TPB_G];
    float mpx[MM / TPB_G], mpy[MM / TPB_G];
    #pragma unroll
    for (int r = 0; r < MM / TPB_G; r++) {
        const int i = tid + r * TPB_G;
        const float px = xb[(size_t)i * CC + 0];
        const float py = xb[(size_t)i * CC + 1];
        const int c = cell_of(py) * GG + cell_of(px);
        myc[r] = c; mpx[r] = px; mpy[r] = py;
        atomicAdd(&s_cnt[c], 1);
    }
    __syncthreads();

    s_scan[tid] = (tid < NCELL) ? s_cnt[tid] : 0;
    __syncthreads();
    for (int off = 1; off < TPB_G; off <<= 1) {
        int v = (tid >= off) ? s_scan[tid - off] : 0;
        __syncthreads();
        s_scan[tid] += v;
        __syncthreads();
    }
    if (tid < NCELL) {
        int excl = s_scan[tid] - s_cnt[tid];
        s_cur[tid] = excl;
        g_cell_off[b * (NCELL + 1) + tid] = excl;
    }
    if (tid == 0) g_cell_off[b * (NCELL + 1) + NCELL] = MM;
    __syncthreads();

    #pragma unroll
    for (int r = 0; r < MM / TPB_G; r++) {
        const int i = tid + r * TPB_G;
        const int slot = atomicAdd(&s_cur[myc[r]], 1);
        g_sorted[(size_t)b * MM + slot] =
            make_float4(mpx[r], mpy[r], __int_as_float(i), 0.0f);
    }
}

// ---------------------------------------------------------------------------
// Fused kernel: NP=4 particles per 256-thread block.
//  Phase 1: warps 0..3 do lane-parallel neighbor search + feature gather
//           into shared memory (feature-major, conflict-free).
//  Phase 2: 2 warps per particle, 2 hidden units per lane (w1 regs halved),
//           pure smem+FMA edge loop (W1[11] folded into W1[2]).
//  Phase 3: 4 threads finish the scalar particle updates.
// ---------------------------------------------------------------------------
__global__ void __launch_bounds__(256, 4) fused_kernel(
    const float* __restrict__ x,  const float* __restrict__ W1,
    const float* __restrict__ b1, const float* __restrict__ W2,
    const float* __restrict__ b2, const float* __restrict__ noise_u,
    float* __restrict__ out)
{
    __shared__ float s_cdx[NP][CAP], s_cdy[NP][CAP], s_cds[NP][CAP];
    __shared__ int   s_cj [NP][CAP];
    __shared__ float s_feat[NP][8][KK];          // feature-major: [field][edge]
    __shared__ int   s_astart[NP][9];
    __shared__ int   s_bound [NP][10];
    __shared__ int   s_cnt[NP], s_deg[NP], s_grow[NP], s_iscell[NP];
    __shared__ float s_px[NP], s_py[NP];
    __shared__ float s_o0[NP][2], s_o1[NP][2];

    const unsigned FULL = 0xffffffffu;
    const int warp = threadIdx.x >> 5;
    const int lane = threadIdx.x & 31;

    // ======================= Phase 1: search (warps 0..3) ====================
    if (warp < NP) {
        const int p = warp;
        const int s = blockIdx.x * NP + p;           // global sorted slot
        const int b = s / MM;
        const int myslot = s - b * MM;

        const float4 me = g_sorted[s];
        const float pix = me.x, piy = me.y;
        const int   myid = __float_as_int(me.z);

        const int cix = cell_of(pix);
        const int ciy = cell_of(piy);
        int len = 0, t0 = 0;
        if (lane < 9) {
            int cy = ciy + (lane / 3) - 1; if (cy < 0) cy += GG; if (cy >= GG) cy -= GG;
            int cx = cix + (lane % 3) - 1; if (cx < 0) cx += GG; if (cx >= GG) cx -= GG;
            const int c = cy * GG + cx;
            t0  = g_cell_off[b * (NCELL + 1) + c];
            len = g_cell_off[b * (NCELL + 1) + c + 1] - t0;
        }
        int incl = len;
        #pragma unroll
        for (int o = 1; o < 16; o <<= 1) {
            int v = __shfl_up_sync(FULL, incl, o);
            if (lane >= o) incl += v;
        }
        const int T = __shfl_sync(FULL, incl, 8);
        if (lane < 9) {
            const int excl = incl - len;
            s_astart[p][lane] = t0 - excl;
            s_bound [p][lane] = excl;
        }
        __syncwarp();

        const float4* __restrict__ sb = g_sorted + (size_t)b * MM;
        int hits = 0;
        for (int base = 0; base < T; base += 32) {
            const int k = base + lane;
            bool pred = false;
            int  cid = 0;
            float dx = 0.f, dy = 0.f, dist = 0.f;
            if (k < T) {
                int q = 0;
                #pragma unroll
                for (int t = 1; t < 9; t++)
                    if (k >= s_bound[p][t]) q = t;
                const int tslot = s_astart[p][q] + k;
                const float4 cand = __ldg(&sb[tslot]);
                dx = pix - cand.x; dx -= rintf(dx);
                dy = piy - cand.y; dy -= rintf(dy);
                dist = sqrtf(dx * dx + dy * dy + 1e-12f);
                pred = (dist < RADIUSF) && (tslot != myslot);
                cid = __float_as_int(cand.z);
            }
            const unsigned m = __ballot_sync(FULL, pred);
            if (pred) {
                const int pos = hits + __popc(m & ((1u << lane) - 1));
                if (pos < CAP) {
                    s_cj [p][pos] = cid;
                    s_cdx[p][pos] = dx;
                    s_cdy[p][pos] = dy;
                    s_cds[p][pos] = dist;
                }
            }
            hits += __popc(m);
        }
        if (hits > CAP) hits = CAP;
        __syncwarp();

        // rare: rank-select KK nearest (order irrelevant: edges are summed)
        if (hits > KK) {
            int rj[2]; float rdx[2], rdy[2], rds[2]; int rk[2];
            int nkeep = 0;
            for (int h = lane; h < hits; h += 32) {
                const float dh = s_cds[p][h];
                int rank = 0;
                for (int g2 = 0; g2 < hits; g2++) {
                    const float dg = s_cds[p][g2];
                    rank += (dg < dh) || (dg == dh && g2 < h);
                }
                if (rank < KK) {
                    rj[nkeep] = s_cj[p][h]; rdx[nkeep] = s_cdx[p][h];
                    rdy[nkeep] = s_cdy[p][h]; rds[nkeep] = dh; rk[nkeep] = rank;
                    nkeep++;
                }
            }
            __syncwarp();
            for (int t = 0; t < nkeep; t++) {
                s_cj [p][rk[t]] = rj[t];
                s_cdx[p][rk[t]] = rdx[t];
                s_cdy[p][rk[t]] = rdy[t];
                s_cds[p][rk[t]] = rds[t];
            }
            hits = KK;
            __syncwarp();
        }

        // feature gather: fields 2..9 of each kept neighbor -> smem (feat-major)
        const int grow = b * MM + myid;
        float c4v = 0.0f;
        if (lane < hits) {
            const int j = s_cj[p][lane];
            const float2* xp = (const float2*)(x + ((size_t)b * MM + j) * CC);
            const float2 a1 = __ldg(&xp[1]);    // vel
            const float2 a2 = __ldg(&xp[2]);    // cell, rest0
            const float2 a3 = __ldg(&xp[3]);
            const float2 a4 = __ldg(&xp[4]);
            s_feat[p][0][lane] = a1.x;  s_feat[p][1][lane] = a1.y;
            s_feat[p][2][lane] = a2.x;  s_feat[p][3][lane] = a2.y;
            s_feat[p][4][lane] = a3.x;  s_feat[p][5][lane] = a3.y;
            s_feat[p][6][lane] = a4.x;  s_feat[p][7][lane] = a4.y;
            c4v = a2.x;
        }
        const int deg = __popc(__ballot_sync(FULL, (lane < hits) && (c4v == 1.0f)));

        if (lane == 0) {
            s_cnt[p] = hits;
            s_deg[p] = deg;
            s_grow[p] = grow;
            s_px[p] = pix;
            s_py[p] = piy;
            s_iscell[p] = (__ldg(&x[(size_t)grow * CC + 4]) == 1.0f) ? 1 : 0;
        }
    }
    __syncthreads();

    // ================= Phase 2: edge MLP (2 warps per particle) ==============
    {
        const int p  = warp >> 1;
        const int hf = warp & 1;
        const int cnt = s_cnt[p];
        float pa0 = 0.0f, pa1 = 0.0f;

        if (s_iscell[p] && cnt > 0) {
            // hidden units h_r = hf*64 + r*32 + lane, r in {0,1}
            const int h0 = hf * 64 + lane;
            const int h1 = h0 + 32;
            float w0[11], w1v[11];
            #pragma unroll
            for (int f = 0; f < 11; f++) {
                w0[f]  = __ldg(&W1[f * HH + h0]);
                w1v[f] = __ldg(&W1[f * HH + h1]);
            }
            // fold duplicated feature: msg[11] == msg[2] (cell flag)
            w0[2]  += __ldg(&W1[11 * HH + h0]);
            w1v[2] += __ldg(&W1[11 * HH + h1]);
            const float bb0 = __ldg(&b1[h0]);
            const float bb1 = __ldg(&b1[h1]);

            float agg0 = 0.0f, agg1 = 0.0f;

            #pragma unroll 2
            for (int e = 0; e < cnt; e++) {
                const float f0 = s_feat[p][0][e], f1 = s_feat[p][1][e];
                const float f2 = s_feat[p][2][e], f3 = s_feat[p][3][e];
                const float f4 = s_feat[p][4][e], f5 = s_feat[p][5][e];
                const float f6 = s_feat[p][6][e], f7 = s_feat[p][7][e];
                const float ds = s_cds[p][e];
                const float dx = s_cdx[p][e], dy = s_cdy[p][e];

                float t0 = bb0, t1 = bb1;
                t0 = fmaf(f0, w0[0], t0);  t1 = fmaf(f0, w1v[0], t1);
                t0 = fmaf(f1, w0[1], t0);  t1 = fmaf(f1, w1v[1], t1);
                t0 = fmaf(f2, w0[2], t0);  t1 = fmaf(f2, w1v[2], t1);
                t0 = fmaf(f3, w0[3], t0);  t1 = fmaf(f3, w1v[3], t1);
                t0 = fmaf(f4, w0[4], t0);  t1 = fmaf(f4, w1v[4], t1);
                t0 = fmaf(f5, w0[5], t0);  t1 = fmaf(f5, w1v[5], t1);
                t0 = fmaf(f6, w0[6], t0);  t1 = fmaf(f6, w1v[6], t1);
                t0 = fmaf(f7, w0[7], t0);  t1 = fmaf(f7, w1v[7], t1);
                t0 = fmaf(ds, w0[8], t0);  t1 = fmaf(ds, w1v[8], t1);
                t0 = fmaf(dx, w0[9], t0);  t1 = fmaf(dx, w1v[9], t1);
                t0 = fmaf(dy, w0[10], t0); t1 = fmaf(dy, w1v[10], t1);
                agg0 += fmaxf(t0, 0.0f);
                agg1 += fmaxf(t1, 0.0f);
            }

            pa0 = fmaf(agg0, __ldg(&W2[h0 * 7 + 0]), agg1 * __ldg(&W2[h1 * 7 + 0]));
            pa1 = fmaf(agg0, __ldg(&W2[h0 * 7 + 1]), agg1 * __ldg(&W2[h1 * 7 + 1]));
            #pragma unroll
            for (int sh = 16; sh > 0; sh >>= 1) {
                pa0 += __shfl_xor_sync(FULL, pa0, sh);
                pa1 += __shfl_xor_sync(FULL, pa1, sh);
            }
        }
        if (lane == 0) { s_o0[p][hf] = pa0; s_o1[p][hf] = pa1; }
    }
    __syncthreads();

    // ================== Phase 3: scalar epilogue (4 threads) =================
    if (threadIdx.x < NP) {
        const int p = threadIdx.x;
        const int grow = s_grow[p];
        const float* xi = x + (size_t)grow * CC;
        const bool is_cell = s_iscell[p] != 0;
        const int  deg_cell = s_deg[p];
        const float pix = s_px[p], piy = s_py[p];
        const float vx = xi[2], vy = xi[3];
        float nvx = vx, nvy = vy, npx = pix, npy = piy;

        if (is_cell) {
            const float o0 = s_o0[p][0] + s_o0[p][1] + __ldg(&b2[0]);
            const float o1 = s_o1[p][0] + s_o1[p][1] + __ldg(&b2[1]);
            float ax = tanhf(o0) * ACC_SCALEF;
            float ay = tanhf(o1) * ACC_SCALEF;
            float ux = vx + ax, uy = vy + ay;
            float sp = sqrtf(ux * ux + uy * uy);
            float sc = fminf(1.0f, MAX_VELF / (sp + 1e-12f));
            ux *= sc; uy *= sc;
            npx = pix + ux; npx -= floorf(npx);
            npy = piy + uy; npy -= floorf(npy);
            const float* nu = noise_u + (size_t)grow * 3;
            const float u0 = nu[0], u1 = nu[1], u2 = nu[2];
            const float nm = (u2 > 0.5f) ? 1.0f : 0.0f;
            nvx = ux + (u0 * 2.0f - 1.0f) * NOISEF * nm;
            nvy = uy + (u1 * 2.0f - 1.0f) * NOISEF * nm;
        }

        const bool dead     =  is_cell && (deg_cell < 1);
        const bool consumed = !is_cell && (deg_cell >= 1);
        const float keep = (dead || consumed) ? 0.0f : 1.0f;

        float* o = out + (size_t)grow * CC;
        o[0] = npx * keep; o[1] = npy * keep;
        o[2] = nvx * keep; o[3] = nvy * keep;
        o[4] = xi[4] * keep;
        o[5] = xi[5] * keep;
        o[6] = xi[6] * keep;
        o[7] = xi[7] * keep;
        o[8] = xi[8] * keep;
        o[9] = xi[9] * keep;
    }
}

// ---------------------------------------------------------------------------
extern "C" void kernel_launch(void* const* d_in, const int* in_sizes, int n_in,
                              void* d_out, int out_size)
{
    const float* x       = (const float*)d_in[0];
    const float* W1      = (const float*)d_in[1];
    const float* b1      = (const float*)d_in[2];
    const float* W2      = (const float*)d_in[3];
    const float* b2      = (const float*)d_in[4];
    const float* noise_u = (const float*)d_in[5];
    float* out = (float*)d_out;

    build_grid_kernel<<<BB, TPB_G>>>(x);
    fused_kernel<<<(BB * MM) / NP, 256>>>(x, W1, b1, W2, b2, noise_u, out);
}

// round 5
// speedup vs baseline: 6.4354x; 1.1448x over previous
#include <cuda_runtime.h>
#include <math.h>

#define BB 8
#define MM 3072
#define CC 10
#define HH 128
#define KK 32
#define GG 24                 // grid cells per axis; 1/24 > 0.04 radius
#define NCELL (GG * GG)       // 576
#define CAP 64                // per-particle hit capacity
#define NPW 8                 // particles (=warps) per 256-thread block
#define RADIUSF 0.04f
#define ACC_SCALEF 0.02f
#define MAX_VELF 0.02f
#define NOISEF 0.002f

typedef unsigned long long ull;

// Scratch (no cudaMalloc allowed)
__device__ float4 g_sorted[BB * MM];            // {x, y, id_as_float_bits, pad}
__device__ int    g_cell_off[BB * (NCELL + 1)]; // exclusive offsets per batch

__device__ __forceinline__ int cell_of(float p) {
    int c = (int)(p * (float)GG);
    return c > GG - 1 ? GG - 1 : c;
}

// ---- f32x2 packed helpers (sm_100+) ---------------------------------------
__device__ __forceinline__ ull pack2(float lo, float hi) {
    ull d; asm("mov.b64 %0, {%1, %2};" : "=l"(d) : "f"(lo), "f"(hi)); return d;
}
__device__ __forceinline__ void unpack2(ull v, float &lo, float &hi) {
    asm("mov.b64 {%0, %1}, %2;" : "=f"(lo), "=f"(hi) : "l"(v));
}
__device__ __forceinline__ ull fma2(ull a, ull b, ull c) {
    ull d; asm("fma.rn.f32x2 %0, %1, %2, %3;" : "=l"(d) : "l"(a), "l"(b), "l"(c));
    return d;
}
__device__ __forceinline__ void lds2x64(ull &a, ull &b, unsigned addr) {
    asm volatile("ld.shared.v2.b64 {%0, %1}, [%2];" : "=l"(a), "=l"(b) : "r"(addr));
}
__device__ __forceinline__ unsigned smem_u32(const void* p) {
    return (unsigned)__cvta_generic_to_shared(p);
}

// ---------------------------------------------------------------------------
// Kernel 0: build cell-sorted particle list. One block per batch.
// ---------------------------------------------------------------------------
#define TPB_G 1024
__global__ void __launch_bounds__(TPB_G) build_grid_kernel(const float* __restrict__ x)
{
    __shared__ int s_cnt[NCELL];
    __shared__ int s_wsum[TPB_G / 32];
    __shared__ int s_cur[NCELL];

    const int b = blockIdx.x;
    const int tid = threadIdx.x;
    const int wid = tid >> 5, lane = tid & 31;
    const unsigned FULL = 0xffffffffu;
    const float* xb = x + (size_t)b * MM * CC;

    if (tid < NCELL) s_cnt[tid] = 0;
    __syncthreads();

    int   myc[MM / TPB_G];
    float mpx[MM / TPB_G], mpy[MM / TPB_G];
    #pragma unroll
    for (int r = 0; r < MM / TPB_G; r++) {
        const int i = tid + r * TPB_G;
        const float px = xb[(size_t)i * CC + 0];
        const float py = xb[(size_t)i * CC + 1];
        const int c = cell_of(py) * GG + cell_of(px);
        myc[r] = c; mpx[r] = px; mpy[r] = py;
        atomicAdd(&s_cnt[c], 1);
    }
    __syncthreads();

    // hierarchical exclusive scan over NCELL=576 (18 warps of counts)
    int val = (tid < NCELL) ? s_cnt[tid] : 0;
    int incl = val;
    #pragma unroll
    for (int o = 1; o < 32; o <<= 1) {
        int v = __shfl_up_sync(FULL, incl, o);
        if (lane >= o) incl += v;
    }
    if (lane == 31) s_wsum[wid] = incl;
    __syncthreads();
    if (wid == 0) {
        int wv = (lane < TPB_G / 32) ? s_wsum[lane] : 0;
        int wi = wv;
        #pragma unroll
        for (int o = 1; o < 32; o <<= 1) {
            int v = __shfl_up_sync(FULL, wi, o);
            if (lane >= o) wi += v;
        }
        if (lane < TPB_G / 32) s_wsum[lane] = wi - wv;   // exclusive warp offsets
    }
    __syncthreads();
    if (tid < NCELL) {
        const int excl = s_wsum[wid] + incl - val;
        s_cur[tid] = excl;
        g_cell_off[b * (NCELL + 1) + tid] = excl;
    }
    if (tid == 0) g_cell_off[b * (NCELL + 1) + NCELL] = MM;
    __syncthreads();

    #pragma unroll
    for (int r = 0; r < MM / TPB_G; r++) {
        const int i = tid + r * TPB_G;
        const int slot = atomicAdd(&s_cur[myc[r]], 1);
        g_sorted[(size_t)b * MM + slot] =
            make_float4(mpx[r], mpy[r], __int_as_float(i), 0.0f);
    }
}

// ---------------------------------------------------------------------------
// Fused kernel: one warp per particle, fully warp-autonomous (no block syncs).
//  Search: lane-parallel 3x3-cell scan -> per-warp smem hit lists.
//  Gather: lane-per-edge, writes DUPLICATED feature pairs (f,f) to smem.
//  MLP:    4 hidden/lane as 2 f32x2 pairs; 22 FFMA2 per edge; W1[11] folded
//          into W1[2] (msg[11]==msg[2]).
// ---------------------------------------------------------------------------
__global__ void __launch_bounds__(256, 3) fused_kernel(
    const float* __restrict__ x,  const float* __restrict__ W1,
    const float* __restrict__ b1, const float* __restrict__ W2,
    const float* __restrict__ b2, const float* __restrict__ noise_u,
    float* __restrict__ out)
{
    __shared__ float s_cdx[NPW][CAP], s_cdy[NPW][CAP], s_cds[NPW][CAP];
    __shared__ int   s_cj [NPW][CAP];
    __shared__ __align__(16) float s_feat[NPW][KK * 24];  // 12 dup-pairs per edge
    __shared__ int   s_astart[NPW][9];
    __shared__ int   s_bound [NPW][10];

    const unsigned FULL = 0xffffffffu;
    const int warp = threadIdx.x >> 5;
    const int lane = threadIdx.x & 31;
    const int p = warp;
    const int s = blockIdx.x * NPW + p;          // global sorted slot
    const int b = s / MM;
    const int myslot = s - b * MM;

    const float4 me = g_sorted[s];
    const float pix = me.x, piy = me.y;
    const int   myid = __float_as_int(me.z);
    const int   grow = b * MM + myid;

    // ======================= Phase 1: search =================================
    const int cix = cell_of(pix);
    const int ciy = cell_of(piy);
    int len = 0, t0 = 0;
    if (lane < 9) {
        int cy = ciy + (lane / 3) - 1; if (cy < 0) cy += GG; if (cy >= GG) cy -= GG;
        int cx = cix + (lane % 3) - 1; if (cx < 0) cx += GG; if (cx >= GG) cx -= GG;
        const int c = cy * GG + cx;
        t0  = g_cell_off[b * (NCELL + 1) + c];
        len = g_cell_off[b * (NCELL + 1) + c + 1] - t0;
    }
    int incl = len;
    #pragma unroll
    for (int o = 1; o < 16; o <<= 1) {
        int v = __shfl_up_sync(FULL, incl, o);
        if (lane >= o) incl += v;
    }
    const int T = __shfl_sync(FULL, incl, 8);
    if (lane < 9) {
        const int excl = incl - len;
        s_astart[p][lane] = t0 - excl;
        s_bound [p][lane] = excl;
    }
    __syncwarp();

    const float4* __restrict__ sb = g_sorted + (size_t)b * MM;
    int hits = 0;
    for (int base = 0; base < T; base += 32) {
        const int k = base + lane;
        bool pred = false;
        int  cid = 0;
        float dx = 0.f, dy = 0.f, dist = 0.f;
        if (k < T) {
            int q = 0;
            #pragma unroll
            for (int t = 1; t < 9; t++)
                if (k >= s_bound[p][t]) q = t;
            const int tslot = s_astart[p][q] + k;
            const float4 cand = __ldg(&sb[tslot]);
            dx = pix - cand.x; dx -= rintf(dx);
            dy = piy - cand.y; dy -= rintf(dy);
            dist = sqrtf(dx * dx + dy * dy + 1e-12f);
            pred = (dist < RADIUSF) && (tslot != myslot);
            cid = __float_as_int(cand.z);
        }
        const unsigned m = __ballot_sync(FULL, pred);
        if (pred) {
            const int pos = hits + __popc(m & ((1u << lane) - 1));
            if (pos < CAP) {
                s_cj [p][pos] = cid;
                s_cdx[p][pos] = dx;
                s_cdy[p][pos] = dy;
                s_cds[p][pos] = dist;
            }
        }
        hits += __popc(m);
    }
    if (hits > CAP) hits = CAP;
    __syncwarp();

    // rare: rank-select KK nearest (edge order irrelevant: edges are summed)
    if (hits > KK) {
        int rj[2]; float rdx[2], rdy[2], rds[2]; int rk[2];
        int nkeep = 0;
        for (int h = lane; h < hits; h += 32) {
            const float dh = s_cds[p][h];
            int rank = 0;
            for (int g2 = 0; g2 < hits; g2++) {
                const float dg = s_cds[p][g2];
                rank += (dg < dh) || (dg == dh && g2 < h);
            }
            if (rank < KK) {
                rj[nkeep] = s_cj[p][h]; rdx[nkeep] = s_cdx[p][h];
                rdy[nkeep] = s_cdy[p][h]; rds[nkeep] = dh; rk[nkeep] = rank;
                nkeep++;
            }
        }
        __syncwarp();
        for (int t = 0; t < nkeep; t++) {
            s_cj [p][rk[t]] = rj[t];
            s_cdx[p][rk[t]] = rdx[t];
            s_cdy[p][rk[t]] = rdy[t];
            s_cds[p][rk[t]] = rds[t];
        }
        hits = KK;
        __syncwarp();
    }
    const int cnt = hits;

    const bool is_cell = (__ldg(&x[(size_t)grow * CC + 4]) == 1.0f);

    // ============== Phase 2: gather features (lane = edge) ===================
    float c4v = 0.0f;
    if (lane < cnt) {
        const int j = s_cj[p][lane];
        const float2* xp = (const float2*)(x + ((size_t)b * MM + j) * CC);
        const float2 a2 = __ldg(&xp[2]);    // cell, rest0
        c4v = a2.x;
        if (is_cell) {
            const float2 a1 = __ldg(&xp[1]);
            const float2 a3 = __ldg(&xp[3]);
            const float2 a4 = __ldg(&xp[4]);
            float2* row = (float2*)&s_feat[p][lane * 24];
            row[0]  = make_float2(a1.x, a1.x);
            row[1]  = make_float2(a1.y, a1.y);
            row[2]  = make_float2(a2.x, a2.x);
            row[3]  = make_float2(a2.y, a2.y);
            row[4]  = make_float2(a3.x, a3.x);
            row[5]  = make_float2(a3.y, a3.y);
            row[6]  = make_float2(a4.x, a4.x);
            row[7]  = make_float2(a4.y, a4.y);
            const float ds = s_cds[p][lane];
            const float dx = s_cdx[p][lane];
            const float dy = s_cdy[p][lane];
            row[8]  = make_float2(ds, ds);
            row[9]  = make_float2(dx, dx);
            row[10] = make_float2(dy, dy);
            row[11] = make_float2(0.f, 0.f);
        }
    }
    const int deg_cell = __popc(__ballot_sync(FULL, (lane < cnt) && (c4v == 1.0f)));
    __syncwarp();

    // ===================== Phase 3: edge MLP (packed) ========================
    float o0 = 0.0f, o1 = 0.0f;

    if (is_cell) {
        float agg0 = 0.f, agg1 = 0.f, agg2 = 0.f, agg3 = 0.f;
        // hidden units: pair A = (lane, lane+32), pair B = (lane+64, lane+96)
        const int hA0 = lane,      hA1 = lane + 32;
        const int hB0 = lane + 64, hB1 = lane + 96;

        if (cnt > 0) {
            ull wA[11], wB[11];
            #pragma unroll
            for (int f = 0; f < 11; f++) {
                wA[f] = pack2(__ldg(&W1[f * HH + hA0]), __ldg(&W1[f * HH + hA1]));
                wB[f] = pack2(__ldg(&W1[f * HH + hB0]), __ldg(&W1[f * HH + hB1]));
            }
            // fold duplicated feature: msg[11] == msg[2]
            wA[2] = fma2(pack2(1.f, 1.f),
                         pack2(__ldg(&W1[11 * HH + hA0]), __ldg(&W1[11 * HH + hA1])), wA[2]);
            wB[2] = fma2(pack2(1.f, 1.f),
                         pack2(__ldg(&W1[11 * HH + hB0]), __ldg(&W1[11 * HH + hB1])), wB[2]);
            const ull bA = pack2(__ldg(&b1[hA0]), __ldg(&b1[hA1]));
            const ull bB = pack2(__ldg(&b1[hB0]), __ldg(&b1[hB1]));

            unsigned raddr = smem_u32(&s_feat[p][0]);
            for (int e = 0; e < cnt; e++, raddr += 96) {
                ull p0, p1, p2, p3, p4, p5, p6, p7, p8, p9, p10, p11;
                lds2x64(p0, p1, raddr);
                lds2x64(p2, p3, raddr + 16);
                lds2x64(p4, p5, raddr + 32);
                lds2x64(p6, p7, raddr + 48);
                lds2x64(p8, p9, raddr + 64);
                lds2x64(p10, p11, raddr + 80);
                (void)p11;

                ull tA = bA, tB = bB;
                tA = fma2(p0,  wA[0],  tA);  tB = fma2(p0,  wB[0],  tB);
                tA = fma2(p1,  wA[1],  tA);  tB = fma2(p1,  wB[1],  tB);
                tA = fma2(p2,  wA[2],  tA);  tB = fma2(p2,  wB[2],  tB);
                tA = fma2(p3,  wA[3],  tA);  tB = fma2(p3,  wB[3],  tB);
                tA = fma2(p4,  wA[4],  tA);  tB = fma2(p4,  wB[4],  tB);
                tA = fma2(p5,  wA[5],  tA);  tB = fma2(p5,  wB[5],  tB);
                tA = fma2(p6,  wA[6],  tA);  tB = fma2(p6,  wB[6],  tB);
                tA = fma2(p7,  wA[7],  tA);  tB = fma2(p7,  wB[7],  tB);
                tA = fma2(p8,  wA[8],  tA);  tB = fma2(p8,  wB[8],  tB);
                tA = fma2(p9,  wA[9],  tA);  tB = fma2(p9,  wB[9],  tB);
                tA = fma2(p10, wA[10], tA);  tB = fma2(p10, wB[10], tB);

                float u0, u1, u2, u3;
                unpack2(tA, u0, u1);
                unpack2(tB, u2, u3);
                agg0 += fmaxf(u0, 0.0f);
                agg1 += fmaxf(u1, 0.0f);
                agg2 += fmaxf(u2, 0.0f);
                agg3 += fmaxf(u3, 0.0f);
            }
        }

        // agg @ W2[:, 0:2]  (outputs 2..6 are dead code in the reference)
        float pa0, pa1;
        pa0 = agg0 * __ldg(&W2[hA0 * 7 + 0]);
        pa0 = fmaf(agg1, __ldg(&W2[hA1 * 7 + 0]), pa0);
        pa0 = fmaf(agg2, __ldg(&W2[hB0 * 7 + 0]), pa0);
        pa0 = fmaf(agg3, __ldg(&W2[hB1 * 7 + 0]), pa0);
        pa1 = agg0 * __ldg(&W2[hA0 * 7 + 1]);
        pa1 = fmaf(agg1, __ldg(&W2[hA1 * 7 + 1]), pa1);
        pa1 = fmaf(agg2, __ldg(&W2[hB0 * 7 + 1]), pa1);
        pa1 = fmaf(agg3, __ldg(&W2[hB1 * 7 + 1]), pa1);
        #pragma unroll
        for (int sh = 16; sh > 0; sh >>= 1) {
            pa0 += __shfl_xor_sync(FULL, pa0, sh);
            pa1 += __shfl_xor_sync(FULL, pa1, sh);
        }
        o0 = pa0 + __ldg(&b2[0]);
        o1 = pa1 + __ldg(&b2[1]);
    }

    // ===================== Phase 4: scalar epilogue ==========================
    if (lane == 0) {
        const float* xi = x + (size_t)grow * CC;
        const float vx = xi[2], vy = xi[3];
        float nvx = vx, nvy = vy, npx = pix, npy = piy;

        if (is_cell) {
            float ax = tanhf(o0) * ACC_SCALEF;
            float ay = tanhf(o1) * ACC_SCALEF;
            float ux = vx + ax, uy = vy + ay;
            float sp = sqrtf(ux * ux + uy * uy);
            float sc = fminf(1.0f, MAX_VELF / (sp + 1e-12f));
            ux *= sc; uy *= sc;
            npx = pix + ux; npx -= floorf(npx);
            npy = piy + uy; npy -= floorf(npy);
            const float* nu = noise_u + (size_t)grow * 3;
            const float u0 = nu[0], u1 = nu[1], u2 = nu[2];
            const float nm = (u2 > 0.5f) ? 1.0f : 0.0f;
            nvx = ux + (u0 * 2.0f - 1.0f) * NOISEF * nm;
            nvy = uy + (u1 * 2.0f - 1.0f) * NOISEF * nm;
        }

        const bool dead     =  is_cell && (deg_cell < 1);
        const bool consumed = !is_cell && (deg_cell >= 1);
        const float keep = (dead || consumed) ? 0.0f : 1.0f;

        float* o = out + (size_t)grow * CC;
        o[0] = npx * keep; o[1] = npy * keep;
        o[2] = nvx * keep; o[3] = nvy * keep;
        o[4] = xi[4] * keep;
        o[5] = xi[5] * keep;
        o[6] = xi[6] * keep;
        o[7] = xi[7] * keep;
        o[8] = xi[8] * keep;
        o[9] = xi[9] * keep;
    }
}

// ---------------------------------------------------------------------------
extern "C" void kernel_launch(void* const* d_in, const int* in_sizes, int n_in,
                              void* d_out, int out_size)
{
    const float* x       = (const float*)d_in[0];
    const float* W1      = (const float*)d_in[1];
    const float* b1      = (const float*)d_in[2];
    const float* W2      = (const float*)d_in[3];
    const float* b2      = (const float*)d_in[4];
    const float* noise_u = (const float*)d_in[5];
    float* out = (float*)d_out;

    build_grid_kernel<<<BB, TPB_G>>>(x);
    fused_kernel<<<(BB * MM) / NPW, 256>>>(x, W1, b1, W2, b2, noise_u, out);
}